// round 1
// baseline (speedup 1.0000x reference)
#include <cuda_runtime.h>
#include <math.h>

#define BB 4
#define NN 2048
#define DD 1024
#define DK 64
#define BN (BB * NN)
#define NSTEPS 4

// ---------------- device scratch (allocation-free rule: __device__ globals) ----------------
__device__ float g_compat[(size_t)BN * NN];   // 64 MB, fits L2
__device__ float g_fpre[BN * 64];
__device__ float g_V[BN * DK];
__device__ float g_Q[BN * DK];
__device__ float g_K[BN * DK];
__device__ float g_charge[BN];
__device__ float g_C[NSTEPS * BN];            // charge snapshots c_1..c_4
__device__ float g_received[BN];
__device__ float g_rowmax[BN];
__device__ float g_rowinv[BN];
__device__ float g_attV[BN * DK];

__device__ __forceinline__ float sigmoidf_(float x) { return 1.0f / (1.0f + __expf(-x)); }

// ---------------- init: zero atomic targets ----------------
__global__ void init_kernel() {
    int idx = blockIdx.x * blockDim.x + threadIdx.x;
    if (idx < BN * DK) g_attV[idx] = 0.0f;
    if (idx < BN) g_received[idx] = 0.0f;
}

// ---------------- GEMM1: hidden[BN,1024] @ [W1;Wv]^T -> fpre(64) | V(64) ----------------
__global__ __launch_bounds__(256) void gemm1_kernel(const float* __restrict__ hidden,
                                                    const float* __restrict__ W1,
                                                    const float* __restrict__ Wv) {
    __shared__ float Ash[32][65];     // [k][m], odd pad -> conflict-free transpose store
    __shared__ float Bsh[32][128];    // [k][n]
    const int tid = threadIdx.x;
    const int m0 = blockIdx.x * 64;
    const int rg = tid >> 5;          // 8 row groups x 8 rows
    const int cg = tid & 31;          // cols cg + 32*j  (conflict-free reads)
    float acc[8][4];
#pragma unroll
    for (int i = 0; i < 8; i++)
#pragma unroll
        for (int j = 0; j < 4; j++) acc[i][j] = 0.0f;

    const int bj = tid & 127;         // B row this thread owns (distinct mod 32 in warp)
    const int bks = tid >> 7;
    const float* wbase = (bj < 64) ? (W1 + (size_t)bj * DD) : (Wv + (size_t)(bj - 64) * DD);

    for (int k0 = 0; k0 < DD; k0 += 32) {
#pragma unroll
        for (int it = 0; it < 2; it++) {
            int q = tid + it * 256;
            int r = q >> 3;
            int kk = (q & 7) << 2;
            float4 v = *(const float4*)(hidden + (size_t)(m0 + r) * DD + k0 + kk);
            Ash[kk + 0][r] = v.x; Ash[kk + 1][r] = v.y;
            Ash[kk + 2][r] = v.z; Ash[kk + 3][r] = v.w;
        }
#pragma unroll
        for (int it = 0; it < 4; it++) {
            int kk = (bks + it * 2) << 2;
            float4 v = *(const float4*)(wbase + k0 + kk);
            Bsh[kk + 0][bj] = v.x; Bsh[kk + 1][bj] = v.y;
            Bsh[kk + 2][bj] = v.z; Bsh[kk + 3][bj] = v.w;
        }
        __syncthreads();
#pragma unroll
        for (int k = 0; k < 32; k++) {
            float ra[8], rb[4];
#pragma unroll
            for (int i = 0; i < 8; i++) ra[i] = Ash[k][rg * 8 + i];
#pragma unroll
            for (int j = 0; j < 4; j++) rb[j] = Bsh[k][cg + 32 * j];
#pragma unroll
            for (int i = 0; i < 8; i++)
#pragma unroll
                for (int j = 0; j < 4; j++) acc[i][j] += ra[i] * rb[j];
        }
        __syncthreads();
    }
#pragma unroll
    for (int i = 0; i < 8; i++) {
        int row = m0 + rg * 8 + i;
#pragma unroll
        for (int j = 0; j < 4; j++) {
            int c = cg + 32 * j;
            if (c < 64) g_fpre[row * 64 + c] = acc[i][j];
            else        g_V[row * DK + (c - 64)] = acc[i][j];
        }
    }
}

// ---------------- per-row tail of the feature net: gelu -> sigmoid MLP -> Q,K,charge ----------------
__global__ __launch_bounds__(128) void feat_kernel(const float* __restrict__ b1,
                                                   const float* __restrict__ W2,
                                                   const float* __restrict__ b2,
                                                   const float* __restrict__ Wq,
                                                   const float* __restrict__ Wk,
                                                   const float* __restrict__ Wc,
                                                   const float* __restrict__ bc) {
    const int bn = blockIdx.x;
    const int tid = threadIdx.x;
    __shared__ float fs[64];
    __shared__ float feat[28];
    if (tid < 64) {
        float x = g_fpre[bn * 64 + tid] + b1[tid];
        fs[tid] = 0.5f * x * (1.0f + erff(x * 0.7071067811865475f));  // exact gelu
    }
    __syncthreads();
    if (tid < 28) {
        float s = b2[tid];
#pragma unroll
        for (int k = 0; k < 64; k++) s += W2[tid * 64 + k] * fs[k];
        feat[tid] = sigmoidf_(s);
    }
    __syncthreads();
    if (tid < 64) {
        float q = 0.f, kv = 0.f;
#pragma unroll
        for (int k = 0; k < 28; k++) {
            float f = feat[k];
            q += Wq[tid * 28 + k] * f;
            kv += Wk[tid * 28 + k] * f;
        }
        g_Q[bn * DK + tid] = q;
        g_K[bn * DK + tid] = kv;
    } else if (tid == 64) {
        float s = bc[0];
#pragma unroll
        for (int k = 0; k < 28; k++) s += Wc[k] * feat[k];
        g_charge[bn] = sigmoidf_(s);
    }
}

// ---------------- compat = Q K^T / 8 over causal tile pairs ----------------
__global__ __launch_bounds__(256) void compat_kernel() {
    const int b = blockIdx.y;
    int t = blockIdx.x;
    int i = 0;
    while ((i + 1) * (i + 2) / 2 <= t) i++;
    int j = t - i * (i + 1) / 2;

    __shared__ float Qsh[64][65];   // [k][r]
    __shared__ float Ksh[64][64];   // [k][c]
    const int tid = threadIdx.x;
    {
        int r = tid >> 4;
        int kk = (tid & 15) << 2;
#pragma unroll
        for (int it = 0; it < 4; it++) {
            int rr = r + it * 16;
            float4 v = *(const float4*)(g_Q + (size_t)(b * NN + i * 64 + rr) * DK + kk);
            Qsh[kk + 0][rr] = v.x; Qsh[kk + 1][rr] = v.y;
            Qsh[kk + 2][rr] = v.z; Qsh[kk + 3][rr] = v.w;
        }
        int jc = tid & 63;
        int ks0 = tid >> 6;
        const float* kb = g_K + (size_t)(b * NN + j * 64 + jc) * DK;
#pragma unroll
        for (int it = 0; it < 4; it++) {
            int k4 = (ks0 + it * 4) << 2;
            float4 v = *(const float4*)(kb + k4);
            Ksh[k4 + 0][jc] = v.x; Ksh[k4 + 1][jc] = v.y;
            Ksh[k4 + 2][jc] = v.z; Ksh[k4 + 3][jc] = v.w;
        }
    }
    __syncthreads();
    const int tr = tid >> 4, tc = tid & 15;
    float acc[4][4] = {{0.f}};
#pragma unroll
    for (int k = 0; k < 64; k++) {
        float ra[4], rb[4];
#pragma unroll
        for (int x = 0; x < 4; x++) ra[x] = Qsh[k][tr * 4 + x];
#pragma unroll
        for (int y = 0; y < 4; y++) rb[y] = Ksh[k][tc + 16 * y];
#pragma unroll
        for (int x = 0; x < 4; x++)
#pragma unroll
            for (int y = 0; y < 4; y++) acc[x][y] += ra[x] * rb[y];
    }
#pragma unroll
    for (int x = 0; x < 4; x++) {
        int n = i * 64 + tr * 4 + x;
        float* dst = g_compat + (size_t)(b * NN + n) * NN + j * 64;
#pragma unroll
        for (int y = 0; y < 4; y++) dst[tc + 16 * y] = acc[x][y] * 0.125f;
    }
}

// ---------------- softmax pass: logits reconstructed as compat*(1 + step*sum c_s c_s) ----------------
// !FINAL: accumulate column sums (received). FINAL: store rowmax & 1/rowsum.
template <bool FINAL>
__global__ __launch_bounds__(256) void pass_kernel(int nc, const float* __restrict__ step_p) {
    __shared__ float row[NN];
    __shared__ float red[8];
    const int bn = blockIdx.x;
    const int b = bn >> 11;
    const int n = bn & (NN - 1);
    const int L = n + 1;
    const int tid = threadIdx.x;
    const float step = *step_p;
    float cn[NSTEPS];
    for (int s = 0; s < nc; s++) cn[s] = g_C[s * BN + bn] * step;
    const float* crow = g_compat + (size_t)bn * NN;
    const float* cb = g_C + b * NN;

    float lmax = -3.4e38f;
    for (int m = tid; m < L; m += 256) {
        float coef = 1.0f;
        for (int s = 0; s < nc; s++) coef += cn[s] * cb[s * BN + m];
        float v = crow[m] * coef;
        row[m] = v;
        lmax = fmaxf(lmax, v);
    }
#pragma unroll
    for (int o = 16; o > 0; o >>= 1) lmax = fmaxf(lmax, __shfl_xor_sync(0xffffffffu, lmax, o));
    if ((tid & 31) == 0) red[tid >> 5] = lmax;
    __syncthreads();
    float bmax = red[0];
#pragma unroll
    for (int w = 1; w < 8; w++) bmax = fmaxf(bmax, red[w]);
    __syncthreads();

    float lsum = 0.0f;
    for (int m = tid; m < L; m += 256) {
        float e = __expf(row[m] - bmax);
        row[m] = e;
        lsum += e;
    }
#pragma unroll
    for (int o = 16; o > 0; o >>= 1) lsum += __shfl_xor_sync(0xffffffffu, lsum, o);
    if ((tid & 31) == 0) red[tid >> 5] = lsum;
    __syncthreads();
    float bsum = red[0] + red[1] + red[2] + red[3] + red[4] + red[5] + red[6] + red[7];

    if (FINAL) {
        if (tid == 0) { g_rowmax[bn] = bmax; g_rowinv[bn] = 1.0f / bsum; }
    } else {
        float inv = 1.0f / bsum;
        float* rcv = g_received + b * NN;
        for (int m = tid; m < L; m += 256) atomicAdd(rcv + m, row[m] * inv);
    }
}

// ---------------- charge update (tiny) ----------------
__global__ void charge_kernel(int p, const float* __restrict__ decay_p) {
    int i = blockIdx.x * blockDim.x + threadIdx.x;
    if (i >= BN) return;
    float decay = *decay_p;
    float r = g_received[i];
    float c = g_charge[i] * (1.0f - decay * sigmoidf_(r - 1.0f));
    g_charge[i] = c;
    g_C[p * BN + i] = c;
    g_received[i] = 0.0f;
}

// ---------------- flash-style attn@V with split-m chunks (atomic merge) ----------------
__global__ __launch_bounds__(256) void attnv_kernel(const float* __restrict__ step_p) {
    const int i = blockIdx.x;      // row tile
    const int b = blockIdx.y;
    const int chunk = blockIdx.z;  // m-tiles j ≡ chunk (mod 4)
    if (chunk > i) return;
    const int n0 = i * 64;
    __shared__ float attnS[64][65];
    __shared__ float Vs[64][64];
    __shared__ float cnS[NSTEPS][64];
    __shared__ float cmS[NSTEPS][64];
    __shared__ float rmaxS[64];
    __shared__ float rinvS[64];
    const int tid = threadIdx.x;
    const float step = *step_p;
    if (tid < 64) {
        int gn = b * NN + n0 + tid;
        rmaxS[tid] = g_rowmax[gn];
        rinvS[tid] = g_rowinv[gn];
#pragma unroll
        for (int s = 0; s < NSTEPS; s++) cnS[s][tid] = g_C[s * BN + gn] * step;
    }
    float acc[4][4] = {{0.f}};
    const int tr = tid >> 4, tc = tid & 15;

    for (int j = chunk; j <= i; j += 4) {
        const int m0 = j * 64;
        __syncthreads();
        if (tid < 64) {
            int gm = b * NN + m0 + tid;
#pragma unroll
            for (int s = 0; s < NSTEPS; s++) cmS[s][tid] = g_C[s * BN + gm];
        }
        {
            int m = tid >> 4;
            int d4 = (tid & 15) << 2;
#pragma unroll
            for (int it = 0; it < 4; it++) {
                int mm = m + it * 16;
                float4 v = *(const float4*)(g_V + (size_t)(b * NN + m0 + mm) * DK + d4);
                Vs[mm][d4 + 0] = v.x; Vs[mm][d4 + 1] = v.y;
                Vs[mm][d4 + 2] = v.z; Vs[mm][d4 + 3] = v.w;
            }
        }
        __syncthreads();
        for (int q = tid; q < 4096; q += 256) {
            int r = q >> 6, m = q & 63;
            int n = n0 + r, mg = m0 + m;
            float v = 0.0f;
            if (mg <= n) {
                float coef = 1.0f;
#pragma unroll
                for (int s = 0; s < NSTEPS; s++) coef += cnS[s][r] * cmS[s][m];
                float lg = g_compat[(size_t)(b * NN + n) * NN + mg] * coef;
                v = __expf(lg - rmaxS[r]) * rinvS[r];
            }
            attnS[r][m] = v;
        }
        __syncthreads();
#pragma unroll 8
        for (int k = 0; k < 64; k++) {
            float ra[4], rb[4];
#pragma unroll
            for (int x = 0; x < 4; x++) ra[x] = attnS[tr * 4 + x][k];
#pragma unroll
            for (int y = 0; y < 4; y++) rb[y] = Vs[k][tc + 16 * y];
#pragma unroll
            for (int x = 0; x < 4; x++)
#pragma unroll
                for (int y = 0; y < 4; y++) acc[x][y] += ra[x] * rb[y];
        }
    }
#pragma unroll
    for (int x = 0; x < 4; x++) {
        float* dst = g_attV + (size_t)(b * NN + n0 + tr * 4 + x) * DK;
#pragma unroll
        for (int y = 0; y < 4; y++) atomicAdd(dst + tc + 16 * y, acc[x][y]);
    }
}

// ---------------- out = 0.1 * attV @ Wo^T ----------------
__global__ __launch_bounds__(256) void outgemm_kernel(const float* __restrict__ Wo,
                                                      float* __restrict__ out) {
    const int mi = blockIdx.x;
    const int ni = blockIdx.y;
    __shared__ float Ash[64][65];   // [k][r]
    __shared__ float Bsh[64][64];   // [k][c]
    const int tid = threadIdx.x;
    {
        int r = tid >> 4;
        int kk = (tid & 15) << 2;
#pragma unroll
        for (int it = 0; it < 4; it++) {
            int rr = r + it * 16;
            float4 v = *(const float4*)(g_attV + (size_t)(mi * 64 + rr) * DK + kk);
            Ash[kk + 0][rr] = v.x; Ash[kk + 1][rr] = v.y;
            Ash[kk + 2][rr] = v.z; Ash[kk + 3][rr] = v.w;
        }
        int jc = tid & 63;
        int ks0 = tid >> 6;
        const float* wb = Wo + (size_t)(ni * 64 + jc) * DK;
#pragma unroll
        for (int it = 0; it < 4; it++) {
            int k4 = (ks0 + it * 4) << 2;
            float4 v = *(const float4*)(wb + k4);
            Bsh[k4 + 0][jc] = v.x; Bsh[k4 + 1][jc] = v.y;
            Bsh[k4 + 2][jc] = v.z; Bsh[k4 + 3][jc] = v.w;
        }
    }
    __syncthreads();
    const int tr = tid >> 4, tc = tid & 15;
    float acc[4][4] = {{0.f}};
#pragma unroll
    for (int k = 0; k < 64; k++) {
        float ra[4], rb[4];
#pragma unroll
        for (int x = 0; x < 4; x++) ra[x] = Ash[k][tr * 4 + x];
#pragma unroll
        for (int y = 0; y < 4; y++) rb[y] = Bsh[k][tc + 16 * y];
#pragma unroll
        for (int x = 0; x < 4; x++)
#pragma unroll
            for (int y = 0; y < 4; y++) acc[x][y] += ra[x] * rb[y];
    }
#pragma unroll
    for (int x = 0; x < 4; x++) {
        size_t base = (size_t)(mi * 64 + tr * 4 + x) * DD + ni * 64;
#pragma unroll
        for (int y = 0; y < 4; y++) out[base + tc + 16 * y] = 0.1f * acc[x][y];
    }
}

// ---------------- launch ----------------
extern "C" void kernel_launch(void* const* d_in, const int* in_sizes, int n_in,
                              void* d_out, int out_size) {
    const float* hidden  = (const float*)d_in[0];
    const float* W1      = (const float*)d_in[1];
    const float* b1      = (const float*)d_in[2];
    const float* W2      = (const float*)d_in[3];
    const float* b2      = (const float*)d_in[4];
    const float* Wq      = (const float*)d_in[5];
    const float* Wk      = (const float*)d_in[6];
    const float* Wc      = (const float*)d_in[7];
    const float* bc      = (const float*)d_in[8];
    const float* Wv      = (const float*)d_in[9];
    const float* Wo      = (const float*)d_in[10];
    const float* step_p  = (const float*)d_in[11];
    const float* decay_p = (const float*)d_in[12];
    float* out = (float*)d_out;

    init_kernel<<<2048, 256>>>();
    gemm1_kernel<<<128, 256>>>(hidden, W1, Wv);
    feat_kernel<<<BN, 128>>>(b1, W2, b2, Wq, Wk, Wc, bc);
    compat_kernel<<<dim3(528, BB), 256>>>();
    for (int p = 0; p < NSTEPS; p++) {
        pass_kernel<false><<<BN, 256>>>(p, step_p);
        charge_kernel<<<BN / 256, 256>>>(p, decay_p);
    }
    pass_kernel<true><<<BN, 256>>>(NSTEPS, step_p);
    attnv_kernel<<<dim3(NN / 64, BB, 4), 256>>>(step_p);
    outgemm_kernel<<<dim3(BN / 64, DD / 64), 256>>>(Wo, out);
}

// round 2
// speedup vs baseline: 1.6701x; 1.6701x over previous
#include <cuda_runtime.h>
#include <math.h>

#define BB 4
#define NN 2048
#define DD 1024
#define DK 64
#define BN (BB * NN)
#define NSTEPS 4
#define KCHUNKS 4

// ---------------- device scratch ----------------
__device__ float  g_compat[(size_t)BN * NN];          // 64 MB
__device__ float  g_part[(size_t)KCHUNKS * BN * 128]; // 16 MB split-k partials
__device__ float  g_fpre[BN * 64];
__device__ float  g_V[BN * DK];
__device__ float  g_Q[BN * DK];
__device__ float  g_K[BN * DK];
__device__ float  g_charge0[BN];
__device__ float4 g_C4[BN];                           // charge snapshots (zero-init each launch)
__device__ float  g_received[BN];
__device__ float  g_rowinv[BN];
__device__ float  g_attV[BN * DK];

__device__ __forceinline__ float sigmoidf_(float x) { return 1.0f / (1.0f + __expf(-x)); }

// ---------------- init: zero accumulators ----------------
__global__ void init_kernel() {
    int idx = blockIdx.x * blockDim.x + threadIdx.x;
    if (idx < BN * DK) g_attV[idx] = 0.0f;
    if (idx < BN) { g_received[idx] = 0.0f; g_C4[idx] = make_float4(0.f, 0.f, 0.f, 0.f); }
}

// ---------------- GEMM1 split-k: hidden[BN,1024] @ [W1;Wv]^T -> partials ----------------
__global__ __launch_bounds__(256) void gemm1_kernel(const float* __restrict__ hidden,
                                                    const float* __restrict__ W1,
                                                    const float* __restrict__ Wv) {
    __shared__ float Ash[32][65];
    __shared__ float Bsh[32][128];
    const int tid = threadIdx.x;
    const int m0 = blockIdx.x * 64;
    const int kc = blockIdx.y;
    const int rg = tid >> 5;
    const int cg = tid & 31;
    float acc[8][4];
#pragma unroll
    for (int i = 0; i < 8; i++)
#pragma unroll
        for (int j = 0; j < 4; j++) acc[i][j] = 0.0f;

    const int bj = tid & 127;
    const int bks = tid >> 7;
    const float* wbase = (bj < 64) ? (W1 + (size_t)bj * DD) : (Wv + (size_t)(bj - 64) * DD);

    const int kbeg = kc * (DD / KCHUNKS);
    const int kend = kbeg + DD / KCHUNKS;
    for (int k0 = kbeg; k0 < kend; k0 += 32) {
#pragma unroll
        for (int it = 0; it < 2; it++) {
            int q = tid + it * 256;
            int r = q >> 3;
            int kk = (q & 7) << 2;
            float4 v = *(const float4*)(hidden + (size_t)(m0 + r) * DD + k0 + kk);
            Ash[kk + 0][r] = v.x; Ash[kk + 1][r] = v.y;
            Ash[kk + 2][r] = v.z; Ash[kk + 3][r] = v.w;
        }
#pragma unroll
        for (int it = 0; it < 4; it++) {
            int kk = (bks + it * 2) << 2;
            float4 v = *(const float4*)(wbase + k0 + kk);
            Bsh[kk + 0][bj] = v.x; Bsh[kk + 1][bj] = v.y;
            Bsh[kk + 2][bj] = v.z; Bsh[kk + 3][bj] = v.w;
        }
        __syncthreads();
#pragma unroll
        for (int k = 0; k < 32; k++) {
            float ra[8], rb[4];
#pragma unroll
            for (int i = 0; i < 8; i++) ra[i] = Ash[k][rg * 8 + i];
#pragma unroll
            for (int j = 0; j < 4; j++) rb[j] = Bsh[k][cg + 32 * j];
#pragma unroll
            for (int i = 0; i < 8; i++)
#pragma unroll
                for (int j = 0; j < 4; j++) acc[i][j] += ra[i] * rb[j];
        }
        __syncthreads();
    }
    float* pbase = g_part + (size_t)kc * BN * 128;
#pragma unroll
    for (int i = 0; i < 8; i++) {
        int row = m0 + rg * 8 + i;
#pragma unroll
        for (int j = 0; j < 4; j++) pbase[(size_t)row * 128 + cg + 32 * j] = acc[i][j];
    }
}

// ---------------- reduce split-k partials -> g_fpre | g_V ----------------
__global__ __launch_bounds__(256) void reduce_kernel() {
    int idx = blockIdx.x * blockDim.x + threadIdx.x;
    if (idx >= BN * 128) return;
    const size_t off = (size_t)BN * 128;
    float s = g_part[idx] + g_part[idx + off] + g_part[idx + 2 * off] + g_part[idx + 3 * off];
    int row = idx >> 7, c = idx & 127;
    if (c < 64) g_fpre[row * 64 + c] = s;
    else        g_V[row * DK + (c - 64)] = s;
}

// ---------------- feature net: gelu -> sigmoid MLP -> Q,K,charge0 (32 rows/block) ----------------
__global__ __launch_bounds__(256) void feat_kernel(const float* __restrict__ b1,
                                                   const float* __restrict__ W2,
                                                   const float* __restrict__ b2,
                                                   const float* __restrict__ Wq,
                                                   const float* __restrict__ Wk,
                                                   const float* __restrict__ Wc,
                                                   const float* __restrict__ bc) {
    __shared__ float W2s[28][65];
    __shared__ float Wqs[64][29];
    __shared__ float Wks[64][29];
    __shared__ float fsS[32][65];
    __shared__ float featS[32][29];
    __shared__ float b1s[64], b2s[28], WcS[28];
    const int tid = threadIdx.x;
    const int r0 = blockIdx.x * 32;

    for (int idx = tid; idx < 28 * 64; idx += 256) W2s[idx >> 6][idx & 63] = W2[idx];
    for (int idx = tid; idx < 64 * 28; idx += 256) {
        int d = idx / 28, k = idx - d * 28;
        Wqs[d][k] = Wq[idx];
        Wks[d][k] = Wk[idx];
    }
    if (tid < 64) b1s[tid] = b1[tid];
    if (tid < 28) { b2s[tid] = b2[tid]; WcS[tid] = Wc[tid]; }
    __syncthreads();

    for (int idx = tid; idx < 32 * 64; idx += 256) {
        int r = idx >> 6, c = idx & 63;
        float x = g_fpre[(r0 + r) * 64 + c] + b1s[c];
        fsS[r][c] = 0.5f * x * (1.0f + erff(x * 0.7071067811865475f));
    }
    __syncthreads();

    {
        int r = tid >> 3, t8 = tid & 7;
        for (int o = t8; o < 28; o += 8) {
            float s = b2s[o];
#pragma unroll
            for (int k = 0; k < 64; k++) s += W2s[o][k] * fsS[r][k];
            featS[r][o] = sigmoidf_(s);
        }
    }
    __syncthreads();

    {
        int r = tid >> 3, t8 = tid & 7;
#pragma unroll
        for (int d = t8; d < 64; d += 8) {
            float q = 0.f, kv = 0.f;
#pragma unroll
            for (int k = 0; k < 28; k++) {
                float f = featS[r][k];
                q  += Wqs[d][k] * f;
                kv += Wks[d][k] * f;
            }
            g_Q[(r0 + r) * DK + d] = q;
            g_K[(r0 + r) * DK + d] = kv;
        }
    }
    if (tid < 32) {
        float s = bc[0];
#pragma unroll
        for (int k = 0; k < 28; k++) s += WcS[k] * featS[tid][k];
        g_charge0[r0 + tid] = sigmoidf_(s);
    }
}

// ---------------- compat = Q K^T / 8 over causal tile pairs ----------------
__global__ __launch_bounds__(256) void compat_kernel() {
    const int b = blockIdx.y;
    int t = blockIdx.x;
    int i = 0;
    while ((i + 1) * (i + 2) / 2 <= t) i++;
    int j = t - i * (i + 1) / 2;

    __shared__ float Qsh[64][65];
    __shared__ float Ksh[64][64];
    const int tid = threadIdx.x;
    {
        int r = tid >> 4;
        int kk = (tid & 15) << 2;
#pragma unroll
        for (int it = 0; it < 4; it++) {
            int rr = r + it * 16;
            float4 v = *(const float4*)(g_Q + (size_t)(b * NN + i * 64 + rr) * DK + kk);
            Qsh[kk + 0][rr] = v.x; Qsh[kk + 1][rr] = v.y;
            Qsh[kk + 2][rr] = v.z; Qsh[kk + 3][rr] = v.w;
        }
        int jc = tid & 63;
        int ks0 = tid >> 6;
        const float* kb = g_K + (size_t)(b * NN + j * 64 + jc) * DK;
#pragma unroll
        for (int it = 0; it < 4; it++) {
            int k4 = (ks0 + it * 4) << 2;
            float4 v = *(const float4*)(kb + k4);
            Ksh[k4 + 0][jc] = v.x; Ksh[k4 + 1][jc] = v.y;
            Ksh[k4 + 2][jc] = v.z; Ksh[k4 + 3][jc] = v.w;
        }
    }
    __syncthreads();
    const int tr = tid >> 4, tc = tid & 15;
    float acc[4][4] = {{0.f}};
#pragma unroll
    for (int k = 0; k < 64; k++) {
        float ra[4], rb[4];
#pragma unroll
        for (int x = 0; x < 4; x++) ra[x] = Qsh[k][tr * 4 + x];
#pragma unroll
        for (int y = 0; y < 4; y++) rb[y] = Ksh[k][tc + 16 * y];
#pragma unroll
        for (int x = 0; x < 4; x++)
#pragma unroll
            for (int y = 0; y < 4; y++) acc[x][y] += ra[x] * rb[y];
    }
#pragma unroll
    for (int x = 0; x < 4; x++) {
        int n = i * 64 + tr * 4 + x;
        float* dst = g_compat + (size_t)(b * NN + n) * NN + j * 64;
#pragma unroll
        for (int y = 0; y < 4; y++) dst[tc + 16 * y] = acc[x][y] * 0.125f;
    }
}

// ---------------- rowsum: 1/sum_m exp(compat*coef). logits tiny -> no max needed ----------------
__global__ __launch_bounds__(128) void rowsum_kernel(const float* __restrict__ step_p) {
    const int bn = blockIdx.x;
    const int b = bn >> 11;
    const int n = bn & (NN - 1);
    const int L = n + 1;
    const int tid = threadIdx.x;
    const float step = *step_p;
    float4 cn = g_C4[bn];
    cn.x *= step; cn.y *= step; cn.z *= step; cn.w *= step;
    const float* crow = g_compat + (size_t)bn * NN;
    const float4* cb = g_C4 + b * NN;

    float s = 0.0f;
    for (int m = tid; m < L; m += 128) {
        float4 cm = cb[m];
        float coef = 1.0f + cn.x * cm.x + cn.y * cm.y + cn.z * cm.z + cn.w * cm.w;
        s += __expf(crow[m] * coef);
    }
#pragma unroll
    for (int o = 16; o > 0; o >>= 1) s += __shfl_xor_sync(0xffffffffu, s, o);
    __shared__ float red[4];
    if ((tid & 31) == 0) red[tid >> 5] = s;
    __syncthreads();
    if (tid == 0) g_rowinv[bn] = 1.0f / (red[0] + red[1] + red[2] + red[3]);
}

// ---------------- colsum: received[m] += sum_n attn[n][m], block-partial per column ----------------
__global__ __launch_bounds__(256) void colsum_kernel(const float* __restrict__ step_p) {
    const int i = blockIdx.x;
    const int b = blockIdx.y;
    const int chunk = blockIdx.z;      // j ≡ chunk (mod 8)
    if (chunk > i) return;
    __shared__ float4 cnS[64];
    __shared__ float4 cmS[64];
    __shared__ float rinvS[64];
    __shared__ float colS[4][64];
    const int tid = threadIdx.x;
    const float step = *step_p;
    if (tid < 64) {
        int gn = b * NN + i * 64 + tid;
        float4 c = g_C4[gn];
        c.x *= step; c.y *= step; c.z *= step; c.w *= step;
        cnS[tid] = c;
        rinvS[tid] = g_rowinv[gn];
    }
    const int c = tid & 63;
    const int rg = tid >> 6;
    for (int j = chunk; j <= i; j += 8) {
        __syncthreads();
        if (tid < 64) cmS[tid] = g_C4[b * NN + j * 64 + tid];
        __syncthreads();
        float4 cm = cmS[c];
        float colsum = 0.0f;
        const float* cbase = g_compat + (size_t)(b * NN + i * 64) * NN + j * 64 + c;
        if (j < i) {
#pragma unroll 4
            for (int rr = 0; rr < 16; rr++) {
                int r = rg + 4 * rr;
                float4 cn = cnS[r];
                float coef = 1.0f + cn.x * cm.x + cn.y * cm.y + cn.z * cm.z + cn.w * cm.w;
                colsum += __expf(cbase[(size_t)r * NN] * coef) * rinvS[r];
            }
        } else {
            for (int rr = 0; rr < 16; rr++) {
                int r = rg + 4 * rr;
                if (c <= r) {
                    float4 cn = cnS[r];
                    float coef = 1.0f + cn.x * cm.x + cn.y * cm.y + cn.z * cm.z + cn.w * cm.w;
                    colsum += __expf(cbase[(size_t)r * NN] * coef) * rinvS[r];
                }
            }
        }
        colS[rg][c] = colsum;
        __syncthreads();
        if (tid < 64) {
            float v = colS[0][tid] + colS[1][tid] + colS[2][tid] + colS[3][tid];
            atomicAdd(g_received + b * NN + j * 64 + tid, v);
        }
    }
}

// ---------------- charge update: fill slot p of g_C4 ----------------
__global__ void charge_kernel(int p, const float* __restrict__ decay_p) {
    int idx = blockIdx.x * blockDim.x + threadIdx.x;
    if (idx >= BN) return;
    float decay = *decay_p;
    float r = g_received[idx];
    float* c4 = (float*)g_C4;
    float cprev = (p == 0) ? g_charge0[idx] : c4[idx * 4 + (p - 1)];
    c4[idx * 4 + p] = cprev * (1.0f - decay * sigmoidf_(r - 1.0f));
    g_received[idx] = 0.0f;
}

// ---------------- flash-style attn@V, split-m chunks with atomic merge ----------------
__global__ __launch_bounds__(256) void attnv_kernel(const float* __restrict__ step_p) {
    const int i = blockIdx.x;
    const int b = blockIdx.y;
    const int chunk = blockIdx.z;
    if (chunk > i) return;
    const int n0 = i * 64;
    __shared__ float attnS[64][65];
    __shared__ float Vs[64][64];
    __shared__ float4 cnS[64];
    __shared__ float4 cmS[64];
    __shared__ float rinvS[64];
    const int tid = threadIdx.x;
    const float step = *step_p;
    if (tid < 64) {
        int gn = b * NN + n0 + tid;
        float4 cc = g_C4[gn];
        cc.x *= step; cc.y *= step; cc.z *= step; cc.w *= step;
        cnS[tid] = cc;
        rinvS[tid] = g_rowinv[gn];
    }
    float acc[4][4] = {{0.f}};
    const int tr = tid >> 4, tc = tid & 15;

    for (int j = chunk; j <= i; j += 4) {
        const int m0 = j * 64;
        __syncthreads();
        if (tid < 64) cmS[tid] = g_C4[b * NN + m0 + tid];
        {
            int m = tid >> 4;
            int d4 = (tid & 15) << 2;
#pragma unroll
            for (int it = 0; it < 4; it++) {
                int mm = m + it * 16;
                float4 v = *(const float4*)(g_V + (size_t)(b * NN + m0 + mm) * DK + d4);
                Vs[mm][d4 + 0] = v.x; Vs[mm][d4 + 1] = v.y;
                Vs[mm][d4 + 2] = v.z; Vs[mm][d4 + 3] = v.w;
            }
        }
        __syncthreads();
        for (int q = tid; q < 4096; q += 256) {
            int r = q >> 6, m = q & 63;
            int n = n0 + r, mg = m0 + m;
            float v = 0.0f;
            if (mg <= n) {
                float4 cn = cnS[r], cm = cmS[m];
                float coef = 1.0f + cn.x * cm.x + cn.y * cm.y + cn.z * cm.z + cn.w * cm.w;
                float lg = g_compat[(size_t)(b * NN + n) * NN + mg] * coef;
                v = __expf(lg) * rinvS[r];
            }
            attnS[r][m] = v;
        }
        __syncthreads();
#pragma unroll 8
        for (int k = 0; k < 64; k++) {
            float ra[4], rb[4];
#pragma unroll
            for (int x = 0; x < 4; x++) ra[x] = attnS[tr * 4 + x][k];
#pragma unroll
            for (int y = 0; y < 4; y++) rb[y] = Vs[k][tc + 16 * y];
#pragma unroll
            for (int x = 0; x < 4; x++)
#pragma unroll
                for (int y = 0; y < 4; y++) acc[x][y] += ra[x] * rb[y];
        }
    }
#pragma unroll
    for (int x = 0; x < 4; x++) {
        float* dst = g_attV + (size_t)(b * NN + n0 + tr * 4 + x) * DK;
#pragma unroll
        for (int y = 0; y < 4; y++) atomicAdd(dst + tc + 16 * y, acc[x][y]);
    }
}

// ---------------- out = 0.1 * attV @ Wo^T ----------------
__global__ __launch_bounds__(256) void outgemm_kernel(const float* __restrict__ Wo,
                                                      float* __restrict__ out) {
    const int mi = blockIdx.x;
    const int ni = blockIdx.y;
    __shared__ float Ash[64][65];
    __shared__ float Bsh[64][64];
    const int tid = threadIdx.x;
    {
        int r = tid >> 4;
        int kk = (tid & 15) << 2;
#pragma unroll
        for (int it = 0; it < 4; it++) {
            int rr = r + it * 16;
            float4 v = *(const float4*)(g_attV + (size_t)(mi * 64 + rr) * DK + kk);
            Ash[kk + 0][rr] = v.x; Ash[kk + 1][rr] = v.y;
            Ash[kk + 2][rr] = v.z; Ash[kk + 3][rr] = v.w;
        }
        int jc = tid & 63;
        int ks0 = tid >> 6;
        const float* wb = Wo + (size_t)(ni * 64 + jc) * DK;
#pragma unroll
        for (int it = 0; it < 4; it++) {
            int k4 = (ks0 + it * 4) << 2;
            float4 v = *(const float4*)(wb + k4);
            Bsh[k4 + 0][jc] = v.x; Bsh[k4 + 1][jc] = v.y;
            Bsh[k4 + 2][jc] = v.z; Bsh[k4 + 3][jc] = v.w;
        }
    }
    __syncthreads();
    const int tr = tid >> 4, tc = tid & 15;
    float acc[4][4] = {{0.f}};
#pragma unroll
    for (int k = 0; k < 64; k++) {
        float ra[4], rb[4];
#pragma unroll
        for (int x = 0; x < 4; x++) ra[x] = Ash[k][tr * 4 + x];
#pragma unroll
        for (int y = 0; y < 4; y++) rb[y] = Bsh[k][tc + 16 * y];
#pragma unroll
        for (int x = 0; x < 4; x++)
#pragma unroll
            for (int y = 0; y < 4; y++) acc[x][y] += ra[x] * rb[y];
    }
#pragma unroll
    for (int x = 0; x < 4; x++) {
        size_t base = (size_t)(mi * 64 + tr * 4 + x) * DD + ni * 64;
#pragma unroll
        for (int y = 0; y < 4; y++) out[base + tc + 16 * y] = 0.1f * acc[x][y];
    }
}

// ---------------- launch ----------------
extern "C" void kernel_launch(void* const* d_in, const int* in_sizes, int n_in,
                              void* d_out, int out_size) {
    const float* hidden  = (const float*)d_in[0];
    const float* W1      = (const float*)d_in[1];
    const float* b1      = (const float*)d_in[2];
    const float* W2      = (const float*)d_in[3];
    const float* b2      = (const float*)d_in[4];
    const float* Wq      = (const float*)d_in[5];
    const float* Wk      = (const float*)d_in[6];
    const float* Wc      = (const float*)d_in[7];
    const float* bc      = (const float*)d_in[8];
    const float* Wv      = (const float*)d_in[9];
    const float* Wo      = (const float*)d_in[10];
    const float* step_p  = (const float*)d_in[11];
    const float* decay_p = (const float*)d_in[12];
    float* out = (float*)d_out;

    init_kernel<<<2048, 256>>>();
    gemm1_kernel<<<dim3(128, KCHUNKS), 256>>>(hidden, W1, Wv);
    reduce_kernel<<<4096, 256>>>();
    feat_kernel<<<BN / 32, 256>>>(b1, W2, b2, Wq, Wk, Wc, bc);
    compat_kernel<<<dim3(528, BB), 256>>>();
    for (int p = 0; p < NSTEPS; p++) {
        rowsum_kernel<<<BN, 128>>>(step_p);
        colsum_kernel<<<dim3(NN / 64, BB, 8), 256>>>(step_p);
        charge_kernel<<<BN / 256, 256>>>(p, decay_p);
    }
    rowsum_kernel<<<BN, 128>>>(step_p);
    attnv_kernel<<<dim3(NN / 64, BB, 4), 256>>>(step_p);
    outgemm_kernel<<<dim3(BN / 64, DD / 64), 256>>>(Wo, out);
}